// round 15
// baseline (speedup 1.0000x reference)
#include <cuda_runtime.h>
#include <math.h>

#define BATCH 8192
typedef unsigned long long ULL;

// ---------------- scratch (device globals) ----------------
__device__ float  d_pool1u [BATCH * 6 * 196];    // [bp][6][14][14] float2
__device__ float  d_pool2u [BATCH * 16 * 25];    // [bp][16][5][5]  float2
__device__ float  d_conv3raw[BATCH * 120];       // [B,120] scalar
__device__ float  d_w2s[16 * 6 * 25];            // binarized conv2 weights
__device__ float  d_w3s[120 * 400];              // binarized conv3 weights
__device__ float  d_w1s[84 * 120];               // binarized fc1 weights
__device__ double d_sum  [142 * 32];             // slotted per-channel sums
__device__ double d_sumsq[142 * 32];
__device__ float  d_bnA[142];
__device__ float  d_bnC[142];

union F2 { ULL u; float2 f; };

__device__ __forceinline__ ULL fma2(ULL a, ULL b, ULL c) {
    ULL d;
    asm("fma.rn.f32x2 %0, %1, %2, %3;" : "=l"(d) : "l"(a), "l"(b), "l"(c));
    return d;
}
__device__ __forceinline__ ULL ld2(const float2* p) { F2 t; t.f = *p; return t.u; }
// one LDS.128 = two f32x2 window positions
__device__ __forceinline__ void ld4(const float2* p, ULL& a, ULL& b) {
    float4 q = *(const float4*)p;
    F2 x; x.f = make_float2(q.x, q.y); a = x.u;
    F2 y; y.f = make_float2(q.z, q.w); b = y.u;
}
__device__ __forceinline__ ULL dupf(float v) {
    ULL d;
    asm("mov.b64 %0, {%1, %1};" : "=l"(d) : "f"(v));
    return d;
}
__device__ __forceinline__ ULL max2(ULL a, ULL b) {
    F2 x, y, r; x.u = a; y.u = b;
    r.f.x = fmaxf(x.f.x, y.f.x);
    r.f.y = fmaxf(x.f.y, y.f.y);
    return r.u;
}
__device__ __forceinline__ float fsign(float v) {
    return v > 0.f ? 1.f : (v < 0.f ? -1.f : 0.f);
}

// ---------------- prep: zero stats + binarize w2/w3/fc1 ----------------
__global__ void prep_kernel(const float* __restrict__ w2, const float* __restrict__ w3,
                            const float* __restrict__ w1) {
    int stride = gridDim.x * blockDim.x;
    int t = blockIdx.x * blockDim.x + threadIdx.x;
    for (int i = t; i < 142 * 32; i += stride) { d_sum[i] = 0.0; d_sumsq[i] = 0.0; }
    for (int i = t; i < 2400; i += stride)  d_w2s[i] = fsign(w2[i]);
    for (int i = t; i < 48000; i += stride) d_w3s[i] = fsign(w3[i]);
    for (int i = t; i < 10080; i += stride) d_w1s[i] = fsign(w1[i]);
}

__global__ void finalize_kernel(int off, int cnt, double n, double eps,
                                const float* __restrict__ g,
                                const float* __restrict__ beta) {
    int i = threadIdx.x;
    if (i < cnt) {
        double s = 0.0, s2 = 0.0;
#pragma unroll
        for (int k = 0; k < 32; k++) {
            s  += d_sum  [(off + i) * 32 + k];
            s2 += d_sumsq[(off + i) * 32 + k];
        }
        double m   = s / n;
        double var = s2 / n - m * m;
        double inv = 1.0 / sqrt(var + eps);
        float gamma = g ? fmaxf(g[i], 0.01f) : 1.f;
        float a = (float)inv * gamma;
        d_bnA[off + i] = a;
        d_bnC[off + i] = (beta ? beta[i] : 0.f) - (float)m * a;
    }
}

// ---------------- conv1: 1->6, 5x5 on 32x32; f32x2 + LDS.128 windows ------
__global__ void __launch_bounds__(336, 3) conv1_kernel(const float* __restrict__ x,
                                                       const float* __restrict__ w) {
    __shared__ float2 in_s[32][34];        // stride 34 -> 272B rows (16B aligned)
    __shared__ float2 wdup[152];
    __shared__ float  ps[336], ps2[336];
    int t = threadIdx.x;
    int bp = blockIdx.x;
    int b0 = bp * 2;

    for (int i = t; i < 1024; i += 336) {
        int r = i >> 5, xx = i & 31;
        in_s[r][xx] = make_float2(x[b0 * 1024 + i], x[b0 * 1024 + 1024 + i]);
    }
    if (t < 150) { float wv = w[t]; wdup[t] = make_float2(wv, wv); }
    __syncthreads();

    int c = t / 56, u = t % 56, oy = u >> 1, half = u & 1;
    int base = half * 14;

    ULL acc[14];
#pragma unroll
    for (int i = 0; i < 14; i++) acc[i] = 0ull;

#pragma unroll
    for (int ky = 0; ky < 5; ky++) {
        const float2* src = &in_s[oy + ky][base];
        ULL w0 = ld2(&wdup[c * 25 + ky * 5 + 0]);
        ULL w1 = ld2(&wdup[c * 25 + ky * 5 + 1]);
        ULL w2 = ld2(&wdup[c * 25 + ky * 5 + 2]);
        ULL w3 = ld2(&wdup[c * 25 + ky * 5 + 3]);
        ULL w4 = ld2(&wdup[c * 25 + ky * 5 + 4]);
        ULL r0, r1, r2, r3, r4, r5;
        ld4(src + 0, r0, r1);
        ld4(src + 2, r2, r3);
#pragma unroll
        for (int ox = 0; ox < 14; ox += 2) {
            ld4(src + ox + 4, r4, r5);
            ULL a = acc[ox];
            a = fma2(r0, w0, a);
            a = fma2(r1, w1, a);
            a = fma2(r2, w2, a);
            a = fma2(r3, w3, a);
            a = fma2(r4, w4, a);
            acc[ox] = a;
            ULL b = acc[ox + 1];
            b = fma2(r1, w0, b);
            b = fma2(r2, w1, b);
            b = fma2(r3, w2, b);
            b = fma2(r4, w3, b);
            b = fma2(r5, w4, b);
            acc[ox + 1] = b;
            r0 = r2; r1 = r3; r2 = r4; r3 = r5;
        }
    }

    float s = 0.f, s2 = 0.f;
#pragma unroll
    for (int i = 0; i < 14; i++) {
        F2 a; a.u = acc[i];
        s += a.f.x + a.f.y;
        s2 += a.f.x * a.f.x + a.f.y * a.f.y;
    }
    ps[t] = s; ps2[t] = s2;

    ULL hm[7];
#pragma unroll
    for (int j = 0; j < 7; j++) hm[j] = max2(acc[2 * j], acc[2 * j + 1]);
    unsigned mask = (t >= 320) ? 0x0000FFFFu : 0xFFFFFFFFu;
#pragma unroll
    for (int j = 0; j < 7; j++) {
        ULL o = __shfl_xor_sync(mask, hm[j], 2);
        hm[j] = max2(hm[j], o);
    }
    if ((oy & 1) == 0) {
        float2* g1 = (float2*)d_pool1u;
        float2* op = &g1[(bp * 6 + c) * 196 + (oy >> 1) * 14 + half * 7];
#pragma unroll
        for (int j = 0; j < 7; j++) { F2 m; m.u = hm[j]; op[j] = m.f; }
    }
    __syncthreads();
    if (t < 6) {
        double ds = 0.0, ds2 = 0.0;
#pragma unroll
        for (int i = 0; i < 56; i++) { ds += ps[t * 56 + i]; ds2 += ps2[t * 56 + i]; }
        int slot = bp & 31;
        atomicAdd(&d_sum[t * 32 + slot], ds);
        atomicAdd(&d_sumsq[t * 32 + slot], ds2);
    }
}

// ---------------- conv2: binary 6->16; LDS.128 windows + dup'd weights ----
__global__ void __launch_bounds__(320, 3) conv2_kernel() {
    __shared__ float2 in2[2][6][14][16];   // stride 16 -> 128B rows (aligned)
    __shared__ float2 wd[2400];            // duplicated binarized weights
    __shared__ float  ps[320], ps2[320];
    __shared__ float2 bnAd[6], bnCd[6];
    int t = threadIdx.x;
    int p0 = blockIdx.x * 2;

    if (t < 6) {
        double s = 0.0, s2 = 0.0;
#pragma unroll
        for (int k = 0; k < 32; k++) { s += d_sum[t * 32 + k]; s2 += d_sumsq[t * 32 + k]; }
        double n = (double)BATCH * 784.0;
        double m = s / n, var = s2 / n - m * m;
        float a = (float)(1.0 / sqrt(var + 1e-4));
        float cc = (float)(-m) * a;
        bnAd[t] = make_float2(a, a);
        bnCd[t] = make_float2(cc, cc);
    }
    for (int i = t; i < 2400; i += 320) {
        float wv = d_w2s[i];
        wd[i] = make_float2(wv, wv);
    }
    __syncthreads();

    const float2* g1 = (const float2*)d_pool1u;
    for (int i = t; i < 2352; i += 320) {
        int pl = i / 1176, k = i % 1176;
        int ic = k / 196, rm = k % 196, r = rm / 14, xx = rm % 14;
        F2 v; v.f = g1[(p0 + pl) * 1176 + k];
        F2 A; A.f = bnAd[ic];
        F2 C; C.f = bnCd[ic];
        ULL rr = max2(fma2(A.u, v.u, C.u), 0ull);
        F2 o; o.u = rr;
        in2[pl][ic][r][xx] = o.f;
    }
    __syncthreads();

    int pl = t / 160, u = t % 160, oc = u / 10, oy = u % 10;

    ULL acc[10];
#pragma unroll
    for (int i = 0; i < 10; i++) acc[i] = 0ull;

    for (int ic = 0; ic < 6; ic++) {
        const float2* wb = &wd[(oc * 6 + ic) * 25];
#pragma unroll
        for (int ky = 0; ky < 5; ky++) {
            const float2* src = &in2[pl][ic][oy + ky][0];
            ULL w0 = ld2(wb + ky * 5 + 0);
            ULL w1 = ld2(wb + ky * 5 + 1);
            ULL w2 = ld2(wb + ky * 5 + 2);
            ULL w3 = ld2(wb + ky * 5 + 3);
            ULL w4 = ld2(wb + ky * 5 + 4);
            ULL r0, r1, r2, r3, r4, r5;
            ld4(src + 0, r0, r1);
            ld4(src + 2, r2, r3);
#pragma unroll
            for (int ox = 0; ox < 10; ox += 2) {
                ld4(src + ox + 4, r4, r5);
                ULL a = acc[ox];
                a = fma2(r0, w0, a);
                a = fma2(r1, w1, a);
                a = fma2(r2, w2, a);
                a = fma2(r3, w3, a);
                a = fma2(r4, w4, a);
                acc[ox] = a;
                ULL b = acc[ox + 1];
                b = fma2(r1, w0, b);
                b = fma2(r2, w1, b);
                b = fma2(r3, w2, b);
                b = fma2(r4, w3, b);
                b = fma2(r5, w4, b);
                acc[ox + 1] = b;
                r0 = r2; r1 = r3; r2 = r4; r3 = r5;
            }
        }
    }

    float s = 0.f, s2 = 0.f;
#pragma unroll
    for (int i = 0; i < 10; i++) {
        F2 a; a.u = acc[i];
        s += a.f.x + a.f.y;
        s2 += a.f.x * a.f.x + a.f.y * a.f.y;
    }
    ps[t] = s; ps2[t] = s2;

    ULL hm[5];
#pragma unroll
    for (int j = 0; j < 5; j++) hm[j] = max2(acc[2 * j], acc[2 * j + 1]);
#pragma unroll
    for (int j = 0; j < 5; j++) {
        ULL o = __shfl_xor_sync(0xFFFFFFFFu, hm[j], 1);
        hm[j] = max2(hm[j], o);
    }
    if ((oy & 1) == 0) {
        float2* g2 = (float2*)d_pool2u;
        float2* op = &g2[(p0 + pl) * 400 + oc * 25 + (oy >> 1) * 5];
#pragma unroll
        for (int j = 0; j < 5; j++) { F2 m; m.u = hm[j]; op[j] = m.f; }
    }
    __syncthreads();
    if (t < 32) {
        int ppl = t / 16, occ = t % 16;
        double ds = 0.0, ds2 = 0.0;
#pragma unroll
        for (int i = 0; i < 10; i++) {
            int u2 = ppl * 160 + occ * 10 + i;
            ds += ps[u2]; ds2 += ps2[u2];
        }
        int slot = (p0 + ppl) & 31;
        atomicAdd(&d_sum[(6 + occ) * 32 + slot], ds);
        atomicAdd(&d_sumsq[(6 + occ) * 32 + slot], ds2);
    }
}

// ---------------- conv3: binary GEMM; dbl-buffered smem weights, 8 acc ----
__global__ void __launch_bounds__(256, 3) conv3_kernel(const float* __restrict__ bn2_g,
                                                       const float* __restrict__ bn2_b) {
    extern __shared__ float smem_raw[];
    float* sm_in = smem_raw;                  // [32][402]
    float* wbuf0 = smem_raw + 32 * 402;       // [60][40]
    float* wbuf1 = wbuf0 + 2400;              // [60][40]
    __shared__ float bnA2[16], bnC2[16];
    int t = threadIdx.x;
    int group = blockIdx.x;
    int half = blockIdx.y;

    if (t < 16) {
        double s = 0.0, s2 = 0.0;
#pragma unroll
        for (int k = 0; k < 32; k++) {
            s += d_sum[(6 + t) * 32 + k];
            s2 += d_sumsq[(6 + t) * 32 + k];
        }
        double n = (double)BATCH * 100.0;
        double m = s / n, var = s2 / n - m * m;
        double inv = 1.0 / sqrt(var + 1e-4);
        float gamma = fmaxf(bn2_g[t], 0.01f);
        float a = (float)inv * gamma;
        bnA2[t] = a;
        bnC2[t] = bn2_b[t] - (float)m * a;
    }
    __syncthreads();

    const float2* g2 = (const float2*)d_pool2u;
    for (int i = t; i < 6400; i += 256) {
        int lp = i / 400, k = i % 400;
        int c = k / 25;
        F2 v; v.f = g2[(group * 16 + lp) * 400 + k];
        float a = bnA2[c], cc = bnC2[c];
        sm_in[(2 * lp) * 402 + k]     = fmaxf(fmaf(a, v.f.x, cc), 0.f);
        sm_in[(2 * lp + 1) * 402 + k] = fmaxf(fmaf(a, v.f.y, cc), 0.f);
    }

    const float* wsrc = &d_w3s[half * 60 * 400];
    {
        int i0 = t, i1 = t + 256;
        int oc0 = i0 / 10, q0 = i0 % 10;
        int oc1 = i1 / 10, q1 = i1 % 10;
        ((float4*)wbuf0)[i0] = *((const float4*)&wsrc[oc0 * 400] + q0);
        ((float4*)wbuf0)[i1] = *((const float4*)&wsrc[oc1 * 400] + q1);
        if (t < 88) {
            int i2 = t + 512;
            int oc2 = i2 / 10, q2 = i2 % 10;
            ((float4*)wbuf0)[i2] = *((const float4*)&wsrc[oc2 * 400] + q2);
        }
    }
    __syncthreads();

    int warp = t >> 5, lane = t & 31;
    bool hasB = (warp < 7);
    int ocA = warp * 4;
    int ocB = hasB ? (warp + 8) * 4 : ocA;
    const float2* inp = (const float2*)&sm_in[lane * 402];

    ULL aA[4] = {0ull, 0ull, 0ull, 0ull};
    ULL aB[4] = {0ull, 0ull, 0ull, 0ull};

#pragma unroll 1
    for (int kc = 0; kc < 10; kc++) {
        float* cur = (kc & 1) ? wbuf1 : wbuf0;
        float* nxt = (kc & 1) ? wbuf0 : wbuf1;

        float4 pf0, pf1, pf2;
        if (kc + 1 < 10) {
            const float* ws = wsrc + (kc + 1) * 40;
            int i0 = t, i1 = t + 256;
            pf0 = *((const float4*)&ws[(i0 / 10) * 400] + (i0 % 10));
            pf1 = *((const float4*)&ws[(i1 / 10) * 400] + (i1 % 10));
            if (t < 88) {
                int i2 = t + 512;
                pf2 = *((const float4*)&ws[(i2 / 10) * 400] + (i2 % 10));
            }
        }

        const float2* ip = inp + kc * 20;
        const float4* cw = (const float4*)cur;
#pragma unroll 5
        for (int kk = 0; kk < 10; kk++) {
            ULL v0 = ld2(&ip[2 * kk]);
            ULL v1 = ld2(&ip[2 * kk + 1]);
            float4 qa0 = cw[(ocA + 0) * 10 + kk];
            float4 qa1 = cw[(ocA + 1) * 10 + kk];
            float4 qa2 = cw[(ocA + 2) * 10 + kk];
            float4 qa3 = cw[(ocA + 3) * 10 + kk];
            F2 p0, p1;
            p0.f = make_float2(qa0.x, qa0.y); p1.f = make_float2(qa0.z, qa0.w);
            aA[0] = fma2(v0, p0.u, aA[0]); aA[0] = fma2(v1, p1.u, aA[0]);
            p0.f = make_float2(qa1.x, qa1.y); p1.f = make_float2(qa1.z, qa1.w);
            aA[1] = fma2(v0, p0.u, aA[1]); aA[1] = fma2(v1, p1.u, aA[1]);
            p0.f = make_float2(qa2.x, qa2.y); p1.f = make_float2(qa2.z, qa2.w);
            aA[2] = fma2(v0, p0.u, aA[2]); aA[2] = fma2(v1, p1.u, aA[2]);
            p0.f = make_float2(qa3.x, qa3.y); p1.f = make_float2(qa3.z, qa3.w);
            aA[3] = fma2(v0, p0.u, aA[3]); aA[3] = fma2(v1, p1.u, aA[3]);
            float4 qb0 = cw[(ocB + 0) * 10 + kk];
            float4 qb1 = cw[(ocB + 1) * 10 + kk];
            float4 qb2 = cw[(ocB + 2) * 10 + kk];
            float4 qb3 = cw[(ocB + 3) * 10 + kk];
            p0.f = make_float2(qb0.x, qb0.y); p1.f = make_float2(qb0.z, qb0.w);
            aB[0] = fma2(v0, p0.u, aB[0]); aB[0] = fma2(v1, p1.u, aB[0]);
            p0.f = make_float2(qb1.x, qb1.y); p1.f = make_float2(qb1.z, qb1.w);
            aB[1] = fma2(v0, p0.u, aB[1]); aB[1] = fma2(v1, p1.u, aB[1]);
            p0.f = make_float2(qb2.x, qb2.y); p1.f = make_float2(qb2.z, qb2.w);
            aB[2] = fma2(v0, p0.u, aB[2]); aB[2] = fma2(v1, p1.u, aB[2]);
            p0.f = make_float2(qb3.x, qb3.y); p1.f = make_float2(qb3.z, qb3.w);
            aB[3] = fma2(v0, p0.u, aB[3]); aB[3] = fma2(v1, p1.u, aB[3]);
        }

        if (kc + 1 < 10) {
            ((float4*)nxt)[t] = pf0;
            ((float4*)nxt)[t + 256] = pf1;
            if (t < 88) ((float4*)nxt)[t + 512] = pf2;
        }
        __syncthreads();
    }

    int bimg = group * 32 + lane;
    int slot = group & 31;
#pragma unroll 1
    for (int rr = 0; rr < 2; rr++) {
        if (rr == 1 && !hasB) break;
        int oc0 = half * 60 + (rr ? ocB : ocA);
        float* o = &d_conv3raw[bimg * 120 + oc0];
#pragma unroll
        for (int j = 0; j < 4; j++) {
            F2 a; a.u = rr ? aB[j] : aA[j];
            float aj = a.f.x + a.f.y;
            o[j] = aj;
            double ds = (double)aj;
            double ds2 = (double)aj * (double)aj;
#pragma unroll
            for (int off = 16; off > 0; off >>= 1) {
                ds  += __shfl_xor_sync(0xffffffffu, ds, off);
                ds2 += __shfl_xor_sync(0xffffffffu, ds2, off);
            }
            if (lane == 0) {
                atomicAdd(&d_sum[(22 + oc0 + j) * 32 + slot], ds);
                atomicAdd(&d_sumsq[(22 + oc0 + j) * 32 + slot], ds2);
            }
        }
    }
}

// ---------------- fc: bn3+relu -> binary fc1+relu -> fc2 (R10 plain form) -
__global__ void fc_kernel(const float* __restrict__ fc1b,
                          const float* __restrict__ fc2w, const float* __restrict__ fc2b,
                          float* __restrict__ out) {
    __shared__ float h_s[8][120];
    __shared__ float h1_s[8][84];
    int t = threadIdx.x, warp = t >> 5, lane = t & 31;
    int b = blockIdx.x * 8 + warp;
    for (int k = lane; k < 120; k += 32) {
        float v = d_conv3raw[b * 120 + k];
        h_s[warp][k] = fmaxf(fmaf(d_bnA[22 + k], v, d_bnC[22 + k]), 0.f);
    }
    __syncwarp();
    for (int oc = lane; oc < 84; oc += 32) {
        float acc = fc1b[oc];
        const float4* wr = (const float4*)&d_w1s[oc * 120];
        const float* h = h_s[warp];
#pragma unroll
        for (int kk = 0; kk < 30; kk++) {
            float4 q = wr[kk];
            acc += q.x * h[4 * kk] + q.y * h[4 * kk + 1]
                 + q.z * h[4 * kk + 2] + q.w * h[4 * kk + 3];
        }
        h1_s[warp][oc] = fmaxf(acc, 0.f);
    }
    __syncwarp();
    if (lane < 10) {
        float acc = fc2b[lane];
        const float* wr = &fc2w[lane * 84];
#pragma unroll 4
        for (int k = 0; k < 84; k++) acc += wr[k] * h1_s[warp][k];
        out[b * 10 + lane] = acc;
    }
}

// ---------------- launcher ----------------
extern "C" void kernel_launch(void* const* d_in, const int* in_sizes, int n_in,
                              void* d_out, int out_size) {
    const float* x       = (const float*)d_in[0];
    const float* conv1_w = (const float*)d_in[1];
    const float* conv2_w = (const float*)d_in[3];
    const float* bn2_g   = (const float*)d_in[5];
    const float* bn2_b   = (const float*)d_in[6];
    const float* conv3_w = (const float*)d_in[7];
    const float* bn3_g   = (const float*)d_in[9];
    const float* bn3_b   = (const float*)d_in[10];
    const float* fc1_w   = (const float*)d_in[11];
    const float* fc1_b   = (const float*)d_in[12];
    const float* fc2_w   = (const float*)d_in[13];
    const float* fc2_b   = (const float*)d_in[14];
    float* out = (float*)d_out;
    (void)in_sizes; (void)n_in; (void)out_size;

    const int conv3_smem = (32 * 402 + 2 * 2400) * 4;   // 70656 B
    cudaFuncSetAttribute(conv3_kernel,
                         cudaFuncAttributeMaxDynamicSharedMemorySize, conv3_smem);

    prep_kernel<<<64, 256>>>(conv2_w, conv3_w, fc1_w);

    conv1_kernel<<<BATCH / 2, 336>>>(x, conv1_w);

    conv2_kernel<<<BATCH / 4, 320>>>();          // bn1 folded in

    conv3_kernel<<<dim3(BATCH / 32, 2), 256, conv3_smem>>>(bn2_g, bn2_b);  // bn2 folded

    finalize_kernel<<<1, 128>>>(22, 120, (double)BATCH, 1e-5, bn3_g, bn3_b);

    fc_kernel<<<BATCH / 8, 256>>>(fc1_b, fc2_w, fc2_b, out);
}

// round 16
// speedup vs baseline: 2.0611x; 2.0611x over previous
#include <cuda_runtime.h>
#include <math.h>

#define BATCH 8192
typedef unsigned long long ULL;

// ---------------- scratch (device globals) ----------------
__device__ float  d_pool1u [BATCH * 6 * 196];    // [bp][6][14][14] float2
__device__ float  d_pool2u [BATCH * 16 * 25];    // [bp][16][5][5]  float2
__device__ float  d_conv3raw[BATCH * 120];       // [B,120] scalar
__device__ float  d_w2s[16 * 6 * 25];            // binarized conv2 weights
__device__ float  d_w3s[120 * 400];              // binarized conv3 weights
__device__ float  d_w1s[84 * 120];               // binarized fc1 weights
__device__ double d_sum  [142 * 32];             // slotted per-channel sums
__device__ double d_sumsq[142 * 32];
__device__ float  d_bnA[142];
__device__ float  d_bnC[142];

union F2 { ULL u; float2 f; };

__device__ __forceinline__ ULL fma2(ULL a, ULL b, ULL c) {
    ULL d;
    asm("fma.rn.f32x2 %0, %1, %2, %3;" : "=l"(d) : "l"(a), "l"(b), "l"(c));
    return d;
}
__device__ __forceinline__ ULL ld2(const float2* p) { F2 t; t.f = *p; return t.u; }
__device__ __forceinline__ ULL dupf(float v) {
    ULL d;
    asm("mov.b64 %0, {%1, %1};" : "=l"(d) : "f"(v));
    return d;
}
__device__ __forceinline__ ULL max2(ULL a, ULL b) {
    F2 x, y, r; x.u = a; y.u = b;
    r.f.x = fmaxf(x.f.x, y.f.x);
    r.f.y = fmaxf(x.f.y, y.f.y);
    return r.u;
}
__device__ __forceinline__ float fsign(float v) {
    return v > 0.f ? 1.f : (v < 0.f ? -1.f : 0.f);
}

// ---------------- prep: zero stats + binarize w2/w3/fc1 ----------------
__global__ void prep_kernel(const float* __restrict__ w2, const float* __restrict__ w3,
                            const float* __restrict__ w1) {
    int stride = gridDim.x * blockDim.x;
    int t = blockIdx.x * blockDim.x + threadIdx.x;
    for (int i = t; i < 142 * 32; i += stride) { d_sum[i] = 0.0; d_sumsq[i] = 0.0; }
    for (int i = t; i < 2400; i += stride)  d_w2s[i] = fsign(w2[i]);
    for (int i = t; i < 48000; i += stride) d_w3s[i] = fsign(w3[i]);
    for (int i = t; i < 10080; i += stride) d_w1s[i] = fsign(w1[i]);
}

__global__ void finalize_kernel(int off, int cnt, double n, double eps,
                                const float* __restrict__ g,
                                const float* __restrict__ beta) {
    int i = threadIdx.x;
    if (i < cnt) {
        double s = 0.0, s2 = 0.0;
#pragma unroll
        for (int k = 0; k < 32; k++) {
            s  += d_sum  [(off + i) * 32 + k];
            s2 += d_sumsq[(off + i) * 32 + k];
        }
        double m   = s / n;
        double var = s2 / n - m * m;
        double inv = 1.0 / sqrt(var + eps);
        float gamma = g ? fmaxf(g[i], 0.01f) : 1.f;
        float a = (float)inv * gamma;
        d_bnA[off + i] = a;
        d_bnC[off + i] = (beta ? beta[i] : 0.f) - (float)m * a;
    }
}

// ---------------- conv1: 1->6, 5x5 on 32x32; f32x2 over image pairs -------
__global__ void __launch_bounds__(336, 3) conv1_kernel(const float* __restrict__ x,
                                                       const float* __restrict__ w) {
    __shared__ float2 in_s[32][33];
    __shared__ float2 wdup[152];
    __shared__ float  ps[336], ps2[336];
    int t = threadIdx.x;
    int bp = blockIdx.x;
    int b0 = bp * 2;

    for (int i = t; i < 1024; i += 336) {
        int r = i >> 5, xx = i & 31;
        in_s[r][xx] = make_float2(x[b0 * 1024 + i], x[b0 * 1024 + 1024 + i]);
    }
    if (t < 150) { float wv = w[t]; wdup[t] = make_float2(wv, wv); }
    __syncthreads();

    int c = t / 56, u = t % 56, oy = u >> 1, half = u & 1;
    int base = half * 14;

    ULL acc[14];
#pragma unroll
    for (int i = 0; i < 14; i++) acc[i] = 0ull;

#pragma unroll
    for (int ky = 0; ky < 5; ky++) {
        const float2* src = &in_s[oy + ky][base];
        ULL w0 = ld2(&wdup[c * 25 + ky * 5 + 0]);
        ULL w1 = ld2(&wdup[c * 25 + ky * 5 + 1]);
        ULL w2 = ld2(&wdup[c * 25 + ky * 5 + 2]);
        ULL w3 = ld2(&wdup[c * 25 + ky * 5 + 3]);
        ULL w4 = ld2(&wdup[c * 25 + ky * 5 + 4]);
        ULL r0 = ld2(src + 0), r1 = ld2(src + 1), r2 = ld2(src + 2), r3 = ld2(src + 3);
#pragma unroll
        for (int ox = 0; ox < 14; ox++) {
            ULL r4 = ld2(src + ox + 4);
            ULL a = acc[ox];
            a = fma2(r0, w0, a);
            a = fma2(r1, w1, a);
            a = fma2(r2, w2, a);
            a = fma2(r3, w3, a);
            a = fma2(r4, w4, a);
            acc[ox] = a;
            r0 = r1; r1 = r2; r2 = r3; r3 = r4;
        }
    }

    float s = 0.f, s2 = 0.f;
#pragma unroll
    for (int i = 0; i < 14; i++) {
        F2 a; a.u = acc[i];
        s += a.f.x + a.f.y;
        s2 += a.f.x * a.f.x + a.f.y * a.f.y;
    }
    ps[t] = s; ps2[t] = s2;

    ULL hm[7];
#pragma unroll
    for (int j = 0; j < 7; j++) hm[j] = max2(acc[2 * j], acc[2 * j + 1]);
    unsigned mask = (t >= 320) ? 0x0000FFFFu : 0xFFFFFFFFu;
#pragma unroll
    for (int j = 0; j < 7; j++) {
        ULL o = __shfl_xor_sync(mask, hm[j], 2);
        hm[j] = max2(hm[j], o);
    }
    if ((oy & 1) == 0) {
        float2* g1 = (float2*)d_pool1u;
        float2* op = &g1[(bp * 6 + c) * 196 + (oy >> 1) * 14 + half * 7];
#pragma unroll
        for (int j = 0; j < 7; j++) { F2 m; m.u = hm[j]; op[j] = m.f; }
    }
    __syncthreads();
    if (t < 6) {
        double ds = 0.0, ds2 = 0.0;
#pragma unroll
        for (int i = 0; i < 56; i++) { ds += ps[t * 56 + i]; ds2 += ps2[t * 56 + i]; }
        int slot = bp & 31;
        atomicAdd(&d_sum[t * 32 + slot], ds);
        atomicAdd(&d_sumsq[t * 32 + slot], ds2);
    }
}

// ---------------- conv2: binary 6->16; f32x2 over image pairs -------------
// R14 structure; weights pre-duplicated as (w,w) float2 -> LDS.64 broadcast.
__global__ void __launch_bounds__(320, 4) conv2_kernel() {
    __shared__ float2 in2[2][6][14][15];
    __shared__ float2 wd[2400];            // duplicated binarized weights
    __shared__ float  ps[320], ps2[320];
    __shared__ float2 bnAd[6], bnCd[6];
    int t = threadIdx.x;
    int p0 = blockIdx.x * 2;

    if (t < 6) {
        double s = 0.0, s2 = 0.0;
#pragma unroll
        for (int k = 0; k < 32; k++) { s += d_sum[t * 32 + k]; s2 += d_sumsq[t * 32 + k]; }
        double n = (double)BATCH * 784.0;
        double m = s / n, var = s2 / n - m * m;
        float a = (float)(1.0 / sqrt(var + 1e-4));
        float cc = (float)(-m) * a;
        bnAd[t] = make_float2(a, a);
        bnCd[t] = make_float2(cc, cc);
    }
    for (int i = t; i < 2400; i += 320) {
        float wv = d_w2s[i];
        wd[i] = make_float2(wv, wv);
    }
    __syncthreads();

    const float2* g1 = (const float2*)d_pool1u;
    for (int i = t; i < 2352; i += 320) {
        int pl = i / 1176, k = i % 1176;
        int ic = k / 196, rm = k % 196, r = rm / 14, xx = rm % 14;
        F2 v; v.f = g1[(p0 + pl) * 1176 + k];
        F2 A; A.f = bnAd[ic];
        F2 C; C.f = bnCd[ic];
        ULL rr = max2(fma2(A.u, v.u, C.u), 0ull);
        F2 o; o.u = rr;
        in2[pl][ic][r][xx] = o.f;
    }
    __syncthreads();

    int pl = t / 160, u = t % 160, oc = u / 10, oy = u % 10;

    ULL acc[10];
#pragma unroll
    for (int i = 0; i < 10; i++) acc[i] = 0ull;

    for (int ic = 0; ic < 6; ic++) {
        const float2* wb = &wd[(oc * 6 + ic) * 25];
#pragma unroll
        for (int ky = 0; ky < 5; ky++) {
            const float2* src = &in2[pl][ic][oy + ky][0];
            ULL w0 = ld2(wb + ky * 5 + 0);
            ULL w1 = ld2(wb + ky * 5 + 1);
            ULL w2 = ld2(wb + ky * 5 + 2);
            ULL w3 = ld2(wb + ky * 5 + 3);
            ULL w4 = ld2(wb + ky * 5 + 4);
            ULL r0 = ld2(src + 0), r1 = ld2(src + 1), r2 = ld2(src + 2), r3 = ld2(src + 3);
#pragma unroll
            for (int ox = 0; ox < 10; ox++) {
                ULL r4 = ld2(src + ox + 4);
                ULL a = acc[ox];
                a = fma2(r0, w0, a);
                a = fma2(r1, w1, a);
                a = fma2(r2, w2, a);
                a = fma2(r3, w3, a);
                a = fma2(r4, w4, a);
                acc[ox] = a;
                r0 = r1; r1 = r2; r2 = r3; r3 = r4;
            }
        }
    }

    float s = 0.f, s2 = 0.f;
#pragma unroll
    for (int i = 0; i < 10; i++) {
        F2 a; a.u = acc[i];
        s += a.f.x + a.f.y;
        s2 += a.f.x * a.f.x + a.f.y * a.f.y;
    }
    ps[t] = s; ps2[t] = s2;

    ULL hm[5];
#pragma unroll
    for (int j = 0; j < 5; j++) hm[j] = max2(acc[2 * j], acc[2 * j + 1]);
#pragma unroll
    for (int j = 0; j < 5; j++) {
        ULL o = __shfl_xor_sync(0xFFFFFFFFu, hm[j], 1);
        hm[j] = max2(hm[j], o);
    }
    if ((oy & 1) == 0) {
        float2* g2 = (float2*)d_pool2u;
        float2* op = &g2[(p0 + pl) * 400 + oc * 25 + (oy >> 1) * 5];
#pragma unroll
        for (int j = 0; j < 5; j++) { F2 m; m.u = hm[j]; op[j] = m.f; }
    }
    __syncthreads();
    if (t < 32) {
        int ppl = t / 16, occ = t % 16;
        double ds = 0.0, ds2 = 0.0;
#pragma unroll
        for (int i = 0; i < 10; i++) {
            int u2 = ppl * 160 + occ * 10 + i;
            ds += ps[u2]; ds2 += ps2[u2];
        }
        int slot = (p0 + ppl) & 31;
        atomicAdd(&d_sum[(6 + occ) * 32 + slot], ds);
        atomicAdd(&d_sumsq[(6 + occ) * 32 + slot], ds2);
    }
}

// ---------------- conv3: binary GEMM; dbl-buffered smem weights, 8 acc ----
__global__ void __launch_bounds__(256, 3) conv3_kernel(const float* __restrict__ bn2_g,
                                                       const float* __restrict__ bn2_b) {
    extern __shared__ float smem_raw[];
    float* sm_in = smem_raw;                  // [32][402]
    float* wbuf0 = smem_raw + 32 * 402;       // [60][40]
    float* wbuf1 = wbuf0 + 2400;              // [60][40]
    __shared__ float bnA2[16], bnC2[16];
    int t = threadIdx.x;
    int group = blockIdx.x;
    int half = blockIdx.y;

    if (t < 16) {
        double s = 0.0, s2 = 0.0;
#pragma unroll
        for (int k = 0; k < 32; k++) {
            s += d_sum[(6 + t) * 32 + k];
            s2 += d_sumsq[(6 + t) * 32 + k];
        }
        double n = (double)BATCH * 100.0;
        double m = s / n, var = s2 / n - m * m;
        double inv = 1.0 / sqrt(var + 1e-4);
        float gamma = fmaxf(bn2_g[t], 0.01f);
        float a = (float)inv * gamma;
        bnA2[t] = a;
        bnC2[t] = bn2_b[t] - (float)m * a;
    }
    __syncthreads();

    const float2* g2 = (const float2*)d_pool2u;
    for (int i = t; i < 6400; i += 256) {
        int lp = i / 400, k = i % 400;
        int c = k / 25;
        F2 v; v.f = g2[(group * 16 + lp) * 400 + k];
        float a = bnA2[c], cc = bnC2[c];
        sm_in[(2 * lp) * 402 + k]     = fmaxf(fmaf(a, v.f.x, cc), 0.f);
        sm_in[(2 * lp + 1) * 402 + k] = fmaxf(fmaf(a, v.f.y, cc), 0.f);
    }

    const float* wsrc = &d_w3s[half * 60 * 400];
    {
        int i0 = t, i1 = t + 256;
        int oc0 = i0 / 10, q0 = i0 % 10;
        int oc1 = i1 / 10, q1 = i1 % 10;
        ((float4*)wbuf0)[i0] = *((const float4*)&wsrc[oc0 * 400] + q0);
        ((float4*)wbuf0)[i1] = *((const float4*)&wsrc[oc1 * 400] + q1);
        if (t < 88) {
            int i2 = t + 512;
            int oc2 = i2 / 10, q2 = i2 % 10;
            ((float4*)wbuf0)[i2] = *((const float4*)&wsrc[oc2 * 400] + q2);
        }
    }
    __syncthreads();

    int warp = t >> 5, lane = t & 31;
    bool hasB = (warp < 7);
    int ocA = warp * 4;
    int ocB = hasB ? (warp + 8) * 4 : ocA;
    const float2* inp = (const float2*)&sm_in[lane * 402];

    ULL aA[4] = {0ull, 0ull, 0ull, 0ull};
    ULL aB[4] = {0ull, 0ull, 0ull, 0ull};

#pragma unroll 1
    for (int kc = 0; kc < 10; kc++) {
        float* cur = (kc & 1) ? wbuf1 : wbuf0;
        float* nxt = (kc & 1) ? wbuf0 : wbuf1;

        float4 pf0, pf1, pf2;
        if (kc + 1 < 10) {
            const float* ws = wsrc + (kc + 1) * 40;
            int i0 = t, i1 = t + 256;
            pf0 = *((const float4*)&ws[(i0 / 10) * 400] + (i0 % 10));
            pf1 = *((const float4*)&ws[(i1 / 10) * 400] + (i1 % 10));
            if (t < 88) {
                int i2 = t + 512;
                pf2 = *((const float4*)&ws[(i2 / 10) * 400] + (i2 % 10));
            }
        }

        const float2* ip = inp + kc * 20;
        const float4* cw = (const float4*)cur;
#pragma unroll 5
        for (int kk = 0; kk < 10; kk++) {
            ULL v0 = ld2(&ip[2 * kk]);
            ULL v1 = ld2(&ip[2 * kk + 1]);
            float4 qa0 = cw[(ocA + 0) * 10 + kk];
            float4 qa1 = cw[(ocA + 1) * 10 + kk];
            float4 qa2 = cw[(ocA + 2) * 10 + kk];
            float4 qa3 = cw[(ocA + 3) * 10 + kk];
            F2 p0, p1;
            p0.f = make_float2(qa0.x, qa0.y); p1.f = make_float2(qa0.z, qa0.w);
            aA[0] = fma2(v0, p0.u, aA[0]); aA[0] = fma2(v1, p1.u, aA[0]);
            p0.f = make_float2(qa1.x, qa1.y); p1.f = make_float2(qa1.z, qa1.w);
            aA[1] = fma2(v0, p0.u, aA[1]); aA[1] = fma2(v1, p1.u, aA[1]);
            p0.f = make_float2(qa2.x, qa2.y); p1.f = make_float2(qa2.z, qa2.w);
            aA[2] = fma2(v0, p0.u, aA[2]); aA[2] = fma2(v1, p1.u, aA[2]);
            p0.f = make_float2(qa3.x, qa3.y); p1.f = make_float2(qa3.z, qa3.w);
            aA[3] = fma2(v0, p0.u, aA[3]); aA[3] = fma2(v1, p1.u, aA[3]);
            float4 qb0 = cw[(ocB + 0) * 10 + kk];
            float4 qb1 = cw[(ocB + 1) * 10 + kk];
            float4 qb2 = cw[(ocB + 2) * 10 + kk];
            float4 qb3 = cw[(ocB + 3) * 10 + kk];
            p0.f = make_float2(qb0.x, qb0.y); p1.f = make_float2(qb0.z, qb0.w);
            aB[0] = fma2(v0, p0.u, aB[0]); aB[0] = fma2(v1, p1.u, aB[0]);
            p0.f = make_float2(qb1.x, qb1.y); p1.f = make_float2(qb1.z, qb1.w);
            aB[1] = fma2(v0, p0.u, aB[1]); aB[1] = fma2(v1, p1.u, aB[1]);
            p0.f = make_float2(qb2.x, qb2.y); p1.f = make_float2(qb2.z, qb2.w);
            aB[2] = fma2(v0, p0.u, aB[2]); aB[2] = fma2(v1, p1.u, aB[2]);
            p0.f = make_float2(qb3.x, qb3.y); p1.f = make_float2(qb3.z, qb3.w);
            aB[3] = fma2(v0, p0.u, aB[3]); aB[3] = fma2(v1, p1.u, aB[3]);
        }

        if (kc + 1 < 10) {
            ((float4*)nxt)[t] = pf0;
            ((float4*)nxt)[t + 256] = pf1;
            if (t < 88) ((float4*)nxt)[t + 512] = pf2;
        }
        __syncthreads();
    }

    int bimg = group * 32 + lane;
    int slot = group & 31;
#pragma unroll 1
    for (int rr = 0; rr < 2; rr++) {
        if (rr == 1 && !hasB) break;
        int oc0 = half * 60 + (rr ? ocB : ocA);
        float* o = &d_conv3raw[bimg * 120 + oc0];
#pragma unroll
        for (int j = 0; j < 4; j++) {
            F2 a; a.u = rr ? aB[j] : aA[j];
            float aj = a.f.x + a.f.y;
            o[j] = aj;
            double ds = (double)aj;
            double ds2 = (double)aj * (double)aj;
#pragma unroll
            for (int off = 16; off > 0; off >>= 1) {
                ds  += __shfl_xor_sync(0xffffffffu, ds, off);
                ds2 += __shfl_xor_sync(0xffffffffu, ds2, off);
            }
            if (lane == 0) {
                atomicAdd(&d_sum[(22 + oc0 + j) * 32 + slot], ds);
                atomicAdd(&d_sumsq[(22 + oc0 + j) * 32 + slot], ds2);
            }
        }
    }
}

// ---------------- fc: bn3+relu -> binary fc1+relu -> fc2 (R10 plain form) -
__global__ void fc_kernel(const float* __restrict__ fc1b,
                          const float* __restrict__ fc2w, const float* __restrict__ fc2b,
                          float* __restrict__ out) {
    __shared__ float h_s[8][120];
    __shared__ float h1_s[8][84];
    int t = threadIdx.x, warp = t >> 5, lane = t & 31;
    int b = blockIdx.x * 8 + warp;
    for (int k = lane; k < 120; k += 32) {
        float v = d_conv3raw[b * 120 + k];
        h_s[warp][k] = fmaxf(fmaf(d_bnA[22 + k], v, d_bnC[22 + k]), 0.f);
    }
    __syncwarp();
    for (int oc = lane; oc < 84; oc += 32) {
        float acc = fc1b[oc];
        const float4* wr = (const float4*)&d_w1s[oc * 120];
        const float* h = h_s[warp];
#pragma unroll
        for (int kk = 0; kk < 30; kk++) {
            float4 q = wr[kk];
            acc += q.x * h[4 * kk] + q.y * h[4 * kk + 1]
                 + q.z * h[4 * kk + 2] + q.w * h[4 * kk + 3];
        }
        h1_s[warp][oc] = fmaxf(acc, 0.f);
    }
    __syncwarp();
    if (lane < 10) {
        float acc = fc2b[lane];
        const float* wr = &fc2w[lane * 84];
#pragma unroll 4
        for (int k = 0; k < 84; k++) acc += wr[k] * h1_s[warp][k];
        out[b * 10 + lane] = acc;
    }
}

// ---------------- launcher ----------------
extern "C" void kernel_launch(void* const* d_in, const int* in_sizes, int n_in,
                              void* d_out, int out_size) {
    const float* x       = (const float*)d_in[0];
    const float* conv1_w = (const float*)d_in[1];
    const float* conv2_w = (const float*)d_in[3];
    const float* bn2_g   = (const float*)d_in[5];
    const float* bn2_b   = (const float*)d_in[6];
    const float* conv3_w = (const float*)d_in[7];
    const float* bn3_g   = (const float*)d_in[9];
    const float* bn3_b   = (const float*)d_in[10];
    const float* fc1_w   = (const float*)d_in[11];
    const float* fc1_b   = (const float*)d_in[12];
    const float* fc2_w   = (const float*)d_in[13];
    const float* fc2_b   = (const float*)d_in[14];
    float* out = (float*)d_out;
    (void)in_sizes; (void)n_in; (void)out_size;

    const int conv3_smem = (32 * 402 + 2 * 2400) * 4;   // 70656 B
    cudaFuncSetAttribute(conv3_kernel,
                         cudaFuncAttributeMaxDynamicSharedMemorySize, conv3_smem);

    prep_kernel<<<64, 256>>>(conv2_w, conv3_w, fc1_w);

    conv1_kernel<<<BATCH / 2, 336>>>(x, conv1_w);

    conv2_kernel<<<BATCH / 4, 320>>>();          // bn1 folded in

    conv3_kernel<<<dim3(BATCH / 32, 2), 256, conv3_smem>>>(bn2_g, bn2_b);  // bn2 folded

    finalize_kernel<<<1, 128>>>(22, 120, (double)BATCH, 1e-5, bn3_g, bn3_b);

    fc_kernel<<<BATCH / 8, 256>>>(fc1_b, fc2_w, fc2_b, out);
}

// round 17
// speedup vs baseline: 2.1104x; 1.0239x over previous
#include <cuda_runtime.h>
#include <math.h>

#define BATCH 8192
typedef unsigned long long ULL;

// ---------------- scratch (device globals) ----------------
__device__ float  d_pool1u [BATCH * 6 * 196];    // [bp][6][14][14] float2
__device__ float  d_pool2u [BATCH * 16 * 25];    // [bp][16][5][5]  float2
__device__ float  d_conv3raw[BATCH * 120];       // [B,120] scalar
__device__ float  d_w2s[16 * 6 * 25];            // binarized conv2 weights
__device__ float  d_w3s[120 * 400];              // binarized conv3 weights
__device__ float  d_w1s[84 * 120];               // binarized fc1 weights
__device__ double d_sum  [142 * 32];             // slotted per-channel sums
__device__ double d_sumsq[142 * 32];
__device__ float  d_bnA[142];
__device__ float  d_bnC[142];

union F2 { ULL u; float2 f; };

__device__ __forceinline__ ULL fma2(ULL a, ULL b, ULL c) {
    ULL d;
    asm("fma.rn.f32x2 %0, %1, %2, %3;" : "=l"(d) : "l"(a), "l"(b), "l"(c));
    return d;
}
__device__ __forceinline__ ULL ld2(const float2* p) { F2 t; t.f = *p; return t.u; }
__device__ __forceinline__ ULL dupf(float v) {
    ULL d;
    asm("mov.b64 %0, {%1, %1};" : "=l"(d) : "f"(v));
    return d;
}
__device__ __forceinline__ ULL max2(ULL a, ULL b) {
    F2 x, y, r; x.u = a; y.u = b;
    r.f.x = fmaxf(x.f.x, y.f.x);
    r.f.y = fmaxf(x.f.y, y.f.y);
    return r.u;
}
__device__ __forceinline__ float fsign(float v) {
    return v > 0.f ? 1.f : (v < 0.f ? -1.f : 0.f);
}

// ---------------- prep: zero stats + binarize w2/w3/fc1 ----------------
__global__ void prep_kernel(const float* __restrict__ w2, const float* __restrict__ w3,
                            const float* __restrict__ w1) {
    int stride = gridDim.x * blockDim.x;
    int t = blockIdx.x * blockDim.x + threadIdx.x;
    for (int i = t; i < 142 * 32; i += stride) { d_sum[i] = 0.0; d_sumsq[i] = 0.0; }
    for (int i = t; i < 2400; i += stride)  d_w2s[i] = fsign(w2[i]);
    for (int i = t; i < 48000; i += stride) d_w3s[i] = fsign(w3[i]);
    for (int i = t; i < 10080; i += stride) d_w1s[i] = fsign(w1[i]);
}

__global__ void finalize_kernel(int off, int cnt, double n, double eps,
                                const float* __restrict__ g,
                                const float* __restrict__ beta) {
    int i = threadIdx.x;
    if (i < cnt) {
        double s = 0.0, s2 = 0.0;
#pragma unroll
        for (int k = 0; k < 32; k++) {
            s  += d_sum  [(off + i) * 32 + k];
            s2 += d_sumsq[(off + i) * 32 + k];
        }
        double m   = s / n;
        double var = s2 / n - m * m;
        double inv = 1.0 / sqrt(var + eps);
        float gamma = g ? fmaxf(g[i], 0.01f) : 1.f;
        float a = (float)inv * gamma;
        d_bnA[off + i] = a;
        d_bnC[off + i] = (beta ? beta[i] : 0.f) - (float)m * a;
    }
}

// ---------------- conv1: 1->6, 5x5 on 32x32; f32x2 over image pairs -------
__global__ void __launch_bounds__(336, 3) conv1_kernel(const float* __restrict__ x,
                                                       const float* __restrict__ w) {
    __shared__ float2 in_s[32][33];
    __shared__ float2 wdup[152];
    __shared__ float  ps[336], ps2[336];
    int t = threadIdx.x;
    int bp = blockIdx.x;
    int b0 = bp * 2;

    for (int i = t; i < 1024; i += 336) {
        int r = i >> 5, xx = i & 31;
        in_s[r][xx] = make_float2(x[b0 * 1024 + i], x[b0 * 1024 + 1024 + i]);
    }
    if (t < 150) { float wv = w[t]; wdup[t] = make_float2(wv, wv); }
    __syncthreads();

    int c = t / 56, u = t % 56, oy = u >> 1, half = u & 1;
    int base = half * 14;

    ULL acc[14];
#pragma unroll
    for (int i = 0; i < 14; i++) acc[i] = 0ull;

#pragma unroll
    for (int ky = 0; ky < 5; ky++) {
        const float2* src = &in_s[oy + ky][base];
        ULL w0 = ld2(&wdup[c * 25 + ky * 5 + 0]);
        ULL w1 = ld2(&wdup[c * 25 + ky * 5 + 1]);
        ULL w2 = ld2(&wdup[c * 25 + ky * 5 + 2]);
        ULL w3 = ld2(&wdup[c * 25 + ky * 5 + 3]);
        ULL w4 = ld2(&wdup[c * 25 + ky * 5 + 4]);
        ULL r0 = ld2(src + 0), r1 = ld2(src + 1), r2 = ld2(src + 2), r3 = ld2(src + 3);
#pragma unroll
        for (int ox = 0; ox < 14; ox++) {
            ULL r4 = ld2(src + ox + 4);
            ULL a = acc[ox];
            a = fma2(r0, w0, a);
            a = fma2(r1, w1, a);
            a = fma2(r2, w2, a);
            a = fma2(r3, w3, a);
            a = fma2(r4, w4, a);
            acc[ox] = a;
            r0 = r1; r1 = r2; r2 = r3; r3 = r4;
        }
    }

    float s = 0.f, s2 = 0.f;
#pragma unroll
    for (int i = 0; i < 14; i++) {
        F2 a; a.u = acc[i];
        s += a.f.x + a.f.y;
        s2 += a.f.x * a.f.x + a.f.y * a.f.y;
    }
    ps[t] = s; ps2[t] = s2;

    ULL hm[7];
#pragma unroll
    for (int j = 0; j < 7; j++) hm[j] = max2(acc[2 * j], acc[2 * j + 1]);
    unsigned mask = (t >= 320) ? 0x0000FFFFu : 0xFFFFFFFFu;
#pragma unroll
    for (int j = 0; j < 7; j++) {
        ULL o = __shfl_xor_sync(mask, hm[j], 2);
        hm[j] = max2(hm[j], o);
    }
    if ((oy & 1) == 0) {
        float2* g1 = (float2*)d_pool1u;
        float2* op = &g1[(bp * 6 + c) * 196 + (oy >> 1) * 14 + half * 7];
#pragma unroll
        for (int j = 0; j < 7; j++) { F2 m; m.u = hm[j]; op[j] = m.f; }
    }
    __syncthreads();
    if (t < 6) {
        double ds = 0.0, ds2 = 0.0;
#pragma unroll
        for (int i = 0; i < 56; i++) { ds += ps[t * 56 + i]; ds2 += ps2[t * 56 + i]; }
        int slot = bp & 31;
        atomicAdd(&d_sum[t * 32 + slot], ds);
        atomicAdd(&d_sumsq[t * 32 + slot], ds2);
    }
}

// ---------------- conv2: binary 6->16; f32x2 over image pairs (R14 form) --
__global__ void __launch_bounds__(320, 4) conv2_kernel() {
    __shared__ float2 in2[2][6][14][15];
    __shared__ float  w_s[2400];
    __shared__ float  ps[320], ps2[320];
    __shared__ float2 bnAd[6], bnCd[6];
    int t = threadIdx.x;
    int p0 = blockIdx.x * 2;

    if (t < 6) {
        double s = 0.0, s2 = 0.0;
#pragma unroll
        for (int k = 0; k < 32; k++) { s += d_sum[t * 32 + k]; s2 += d_sumsq[t * 32 + k]; }
        double n = (double)BATCH * 784.0;
        double m = s / n, var = s2 / n - m * m;
        float a = (float)(1.0 / sqrt(var + 1e-4));
        float cc = (float)(-m) * a;
        bnAd[t] = make_float2(a, a);
        bnCd[t] = make_float2(cc, cc);
    }
    for (int i = t; i < 2400; i += 320) w_s[i] = d_w2s[i];
    __syncthreads();

    const float2* g1 = (const float2*)d_pool1u;
    for (int i = t; i < 2352; i += 320) {
        int pl = i / 1176, k = i % 1176;
        int ic = k / 196, rm = k % 196, r = rm / 14, xx = rm % 14;
        F2 v; v.f = g1[(p0 + pl) * 1176 + k];
        F2 A; A.f = bnAd[ic];
        F2 C; C.f = bnCd[ic];
        ULL rr = max2(fma2(A.u, v.u, C.u), 0ull);
        F2 o; o.u = rr;
        in2[pl][ic][r][xx] = o.f;
    }
    __syncthreads();

    int pl = t / 160, u = t % 160, oc = u / 10, oy = u % 10;

    ULL acc[10];
#pragma unroll
    for (int i = 0; i < 10; i++) acc[i] = 0ull;

    for (int ic = 0; ic < 6; ic++) {
        const float* wb = &w_s[(oc * 6 + ic) * 25];
#pragma unroll
        for (int ky = 0; ky < 5; ky++) {
            const float2* src = &in2[pl][ic][oy + ky][0];
            ULL w0 = dupf(wb[ky * 5 + 0]);
            ULL w1 = dupf(wb[ky * 5 + 1]);
            ULL w2 = dupf(wb[ky * 5 + 2]);
            ULL w3 = dupf(wb[ky * 5 + 3]);
            ULL w4 = dupf(wb[ky * 5 + 4]);
            ULL r0 = ld2(src + 0), r1 = ld2(src + 1), r2 = ld2(src + 2), r3 = ld2(src + 3);
#pragma unroll
            for (int ox = 0; ox < 10; ox++) {
                ULL r4 = ld2(src + ox + 4);
                ULL a = acc[ox];
                a = fma2(r0, w0, a);
                a = fma2(r1, w1, a);
                a = fma2(r2, w2, a);
                a = fma2(r3, w3, a);
                a = fma2(r4, w4, a);
                acc[ox] = a;
                r0 = r1; r1 = r2; r2 = r3; r3 = r4;
            }
        }
    }

    float s = 0.f, s2 = 0.f;
#pragma unroll
    for (int i = 0; i < 10; i++) {
        F2 a; a.u = acc[i];
        s += a.f.x + a.f.y;
        s2 += a.f.x * a.f.x + a.f.y * a.f.y;
    }
    ps[t] = s; ps2[t] = s2;

    ULL hm[5];
#pragma unroll
    for (int j = 0; j < 5; j++) hm[j] = max2(acc[2 * j], acc[2 * j + 1]);
#pragma unroll
    for (int j = 0; j < 5; j++) {
        ULL o = __shfl_xor_sync(0xFFFFFFFFu, hm[j], 1);
        hm[j] = max2(hm[j], o);
    }
    if ((oy & 1) == 0) {
        float2* g2 = (float2*)d_pool2u;
        float2* op = &g2[(p0 + pl) * 400 + oc * 25 + (oy >> 1) * 5];
#pragma unroll
        for (int j = 0; j < 5; j++) { F2 m; m.u = hm[j]; op[j] = m.f; }
    }
    __syncthreads();
    if (t < 32) {
        int ppl = t / 16, occ = t % 16;
        double ds = 0.0, ds2 = 0.0;
#pragma unroll
        for (int i = 0; i < 10; i++) {
            int u2 = ppl * 160 + occ * 10 + i;
            ds += ps[u2]; ds2 += ps2[u2];
        }
        int slot = (p0 + ppl) & 31;
        atomicAdd(&d_sum[(6 + occ) * 32 + slot], ds);
        atomicAdd(&d_sumsq[(6 + occ) * 32 + slot], ds2);
    }
}

// ---------------- conv3: binary GEMM; pair-major input (bank-conflict-free)
// sm_in layout: sp[pairIdx][img] as float2, row stride 33 (odd) -> lanes hit
// consecutive banks. 200 pairs * 33 float2 = 6600 float2 = 52.8KB... use
// stride 33: total 200*33*8 = 52800 B; weights 2*9600 = 19200 -> 72000 B.
__global__ void __launch_bounds__(256, 3) conv3_kernel(const float* __restrict__ bn2_g,
                                                       const float* __restrict__ bn2_b) {
    extern __shared__ float smem_raw[];
    float2* sp   = (float2*)smem_raw;              // [200][33] float2
    float* wbuf0 = smem_raw + 200 * 33 * 2;        // [60][40]
    float* wbuf1 = wbuf0 + 2400;                   // [60][40]
    __shared__ float bnA2[16], bnC2[16];
    int t = threadIdx.x;
    int group = blockIdx.x;
    int half = blockIdx.y;

    if (t < 16) {
        double s = 0.0, s2 = 0.0;
#pragma unroll
        for (int k = 0; k < 32; k++) {
            s += d_sum[(6 + t) * 32 + k];
            s2 += d_sumsq[(6 + t) * 32 + k];
        }
        double n = (double)BATCH * 100.0;
        double m = s / n, var = s2 / n - m * m;
        double inv = 1.0 / sqrt(var + 1e-4);
        float gamma = fmaxf(bn2_g[t], 0.01f);
        float a = (float)inv * gamma;
        bnA2[t] = a;
        bnC2[t] = bn2_b[t] - (float)m * a;
    }
    __syncthreads();

    // stage input pair-major: sp[k>>1][img] = (v[2p], v[2p+1]) for image img
    const float2* g2 = (const float2*)d_pool2u;
    for (int i = t; i < 3200; i += 256) {          // 16 img-pairs * 200 k-pairs
        int lp = i / 200, p = i % 200;             // lp: image pair, p: k-pair
        int c0 = (2 * p) / 25, c1 = (2 * p + 1) / 25;
        F2 v0; v0.f = g2[(group * 16 + lp) * 400 + 2 * p];
        F2 v1; v1.f = g2[(group * 16 + lp) * 400 + 2 * p + 1];
        float a0 = bnA2[c0], cc0 = bnC2[c0];
        float a1 = bnA2[c1], cc1 = bnC2[c1];
        // image 2lp gets (v0.x, v1.x); image 2lp+1 gets (v0.y, v1.y)
        sp[p * 33 + 2 * lp]     = make_float2(fmaxf(fmaf(a0, v0.f.x, cc0), 0.f),
                                              fmaxf(fmaf(a1, v1.f.x, cc1), 0.f));
        sp[p * 33 + 2 * lp + 1] = make_float2(fmaxf(fmaf(a0, v0.f.y, cc0), 0.f),
                                              fmaxf(fmaf(a1, v1.f.y, cc1), 0.f));
    }

    const float* wsrc = &d_w3s[half * 60 * 400];
    {
        int i0 = t, i1 = t + 256;
        int oc0 = i0 / 10, q0 = i0 % 10;
        int oc1 = i1 / 10, q1 = i1 % 10;
        ((float4*)wbuf0)[i0] = *((const float4*)&wsrc[oc0 * 400] + q0);
        ((float4*)wbuf0)[i1] = *((const float4*)&wsrc[oc1 * 400] + q1);
        if (t < 88) {
            int i2 = t + 512;
            int oc2 = i2 / 10, q2 = i2 % 10;
            ((float4*)wbuf0)[i2] = *((const float4*)&wsrc[oc2 * 400] + q2);
        }
    }
    __syncthreads();

    int warp = t >> 5, lane = t & 31;
    bool hasB = (warp < 7);
    int ocA = warp * 4;
    int ocB = hasB ? (warp + 8) * 4 : ocA;

    ULL aA[4] = {0ull, 0ull, 0ull, 0ull};
    ULL aB[4] = {0ull, 0ull, 0ull, 0ull};

#pragma unroll 1
    for (int kc = 0; kc < 10; kc++) {
        float* cur = (kc & 1) ? wbuf1 : wbuf0;
        float* nxt = (kc & 1) ? wbuf0 : wbuf1;

        float4 pf0, pf1, pf2;
        if (kc + 1 < 10) {
            const float* ws = wsrc + (kc + 1) * 40;
            int i0 = t, i1 = t + 256;
            pf0 = *((const float4*)&ws[(i0 / 10) * 400] + (i0 % 10));
            pf1 = *((const float4*)&ws[(i1 / 10) * 400] + (i1 % 10));
            if (t < 88) {
                int i2 = t + 512;
                pf2 = *((const float4*)&ws[(i2 / 10) * 400] + (i2 % 10));
            }
        }

        const float2* ip = &sp[(kc * 20) * 33 + lane];  // pair rows, lane column
        const float4* cw = (const float4*)cur;
#pragma unroll 5
        for (int kk = 0; kk < 10; kk++) {
            ULL v0 = ld2(ip + (2 * kk) * 33);
            ULL v1 = ld2(ip + (2 * kk + 1) * 33);
            float4 qa0 = cw[(ocA + 0) * 10 + kk];
            float4 qa1 = cw[(ocA + 1) * 10 + kk];
            float4 qa2 = cw[(ocA + 2) * 10 + kk];
            float4 qa3 = cw[(ocA + 3) * 10 + kk];
            F2 p0, p1;
            p0.f = make_float2(qa0.x, qa0.y); p1.f = make_float2(qa0.z, qa0.w);
            aA[0] = fma2(v0, p0.u, aA[0]); aA[0] = fma2(v1, p1.u, aA[0]);
            p0.f = make_float2(qa1.x, qa1.y); p1.f = make_float2(qa1.z, qa1.w);
            aA[1] = fma2(v0, p0.u, aA[1]); aA[1] = fma2(v1, p1.u, aA[1]);
            p0.f = make_float2(qa2.x, qa2.y); p1.f = make_float2(qa2.z, qa2.w);
            aA[2] = fma2(v0, p0.u, aA[2]); aA[2] = fma2(v1, p1.u, aA[2]);
            p0.f = make_float2(qa3.x, qa3.y); p1.f = make_float2(qa3.z, qa3.w);
            aA[3] = fma2(v0, p0.u, aA[3]); aA[3] = fma2(v1, p1.u, aA[3]);
            float4 qb0 = cw[(ocB + 0) * 10 + kk];
            float4 qb1 = cw[(ocB + 1) * 10 + kk];
            float4 qb2 = cw[(ocB + 2) * 10 + kk];
            float4 qb3 = cw[(ocB + 3) * 10 + kk];
            p0.f = make_float2(qb0.x, qb0.y); p1.f = make_float2(qb0.z, qb0.w);
            aB[0] = fma2(v0, p0.u, aB[0]); aB[0] = fma2(v1, p1.u, aB[0]);
            p0.f = make_float2(qb1.x, qb1.y); p1.f = make_float2(qb1.z, qb1.w);
            aB[1] = fma2(v0, p0.u, aB[1]); aB[1] = fma2(v1, p1.u, aB[1]);
            p0.f = make_float2(qb2.x, qb2.y); p1.f = make_float2(qb2.z, qb2.w);
            aB[2] = fma2(v0, p0.u, aB[2]); aB[2] = fma2(v1, p1.u, aB[2]);
            p0.f = make_float2(qb3.x, qb3.y); p1.f = make_float2(qb3.z, qb3.w);
            aB[3] = fma2(v0, p0.u, aB[3]); aB[3] = fma2(v1, p1.u, aB[3]);
        }

        if (kc + 1 < 10) {
            ((float4*)nxt)[t] = pf0;
            ((float4*)nxt)[t + 256] = pf1;
            if (t < 88) ((float4*)nxt)[t + 512] = pf2;
        }
        __syncthreads();
    }

    // f32x2 lanes now hold (k even, k odd) partial sums for ONE image = lane's
    // image: bimg = group*32 + lane; result = x + y as before.
    int bimg = group * 32 + lane;
    int slot = group & 31;
#pragma unroll 1
    for (int rr = 0; rr < 2; rr++) {
        if (rr == 1 && !hasB) break;
        int oc0 = half * 60 + (rr ? ocB : ocA);
        float* o = &d_conv3raw[bimg * 120 + oc0];
#pragma unroll
        for (int j = 0; j < 4; j++) {
            F2 a; a.u = rr ? aB[j] : aA[j];
            float aj = a.f.x + a.f.y;
            o[j] = aj;
            double ds = (double)aj;
            double ds2 = (double)aj * (double)aj;
#pragma unroll
            for (int off = 16; off > 0; off >>= 1) {
                ds  += __shfl_xor_sync(0xffffffffu, ds, off);
                ds2 += __shfl_xor_sync(0xffffffffu, ds2, off);
            }
            if (lane == 0) {
                atomicAdd(&d_sum[(22 + oc0 + j) * 32 + slot], ds);
                atomicAdd(&d_sumsq[(22 + oc0 + j) * 32 + slot], ds2);
            }
        }
    }
}

// ---------------- fc: bn3+relu -> binary fc1+relu -> fc2 (R10 plain form) -
__global__ void fc_kernel(const float* __restrict__ fc1b,
                          const float* __restrict__ fc2w, const float* __restrict__ fc2b,
                          float* __restrict__ out) {
    __shared__ float h_s[8][120];
    __shared__ float h1_s[8][84];
    int t = threadIdx.x, warp = t >> 5, lane = t & 31;
    int b = blockIdx.x * 8 + warp;
    for (int k = lane; k < 120; k += 32) {
        float v = d_conv3raw[b * 120 + k];
        h_s[warp][k] = fmaxf(fmaf(d_bnA[22 + k], v, d_bnC[22 + k]), 0.f);
    }
    __syncwarp();
    for (int oc = lane; oc < 84; oc += 32) {
        float acc = fc1b[oc];
        const float4* wr = (const float4*)&d_w1s[oc * 120];
        const float* h = h_s[warp];
#pragma unroll
        for (int kk = 0; kk < 30; kk++) {
            float4 q = wr[kk];
            acc += q.x * h[4 * kk] + q.y * h[4 * kk + 1]
                 + q.z * h[4 * kk + 2] + q.w * h[4 * kk + 3];
        }
        h1_s[warp][oc] = fmaxf(acc, 0.f);
    }
    __syncwarp();
    if (lane < 10) {
        float acc = fc2b[lane];
        const float* wr = &fc2w[lane * 84];
#pragma unroll 4
        for (int k = 0; k < 84; k++) acc += wr[k] * h1_s[warp][k];
        out[b * 10 + lane] = acc;
    }
}

// ---------------- launcher ----------------
extern "C" void kernel_launch(void* const* d_in, const int* in_sizes, int n_in,
                              void* d_out, int out_size) {
    const float* x       = (const float*)d_in[0];
    const float* conv1_w = (const float*)d_in[1];
    const float* conv2_w = (const float*)d_in[3];
    const float* bn2_g   = (const float*)d_in[5];
    const float* bn2_b   = (const float*)d_in[6];
    const float* conv3_w = (const float*)d_in[7];
    const float* bn3_g   = (const float*)d_in[9];
    const float* bn3_b   = (const float*)d_in[10];
    const float* fc1_w   = (const float*)d_in[11];
    const float* fc1_b   = (const float*)d_in[12];
    const float* fc2_w   = (const float*)d_in[13];
    const float* fc2_b   = (const float*)d_in[14];
    float* out = (float*)d_out;
    (void)in_sizes; (void)n_in; (void)out_size;

    const int conv3_smem = (200 * 33 * 2 + 2 * 2400) * 4;   // 72000 B
    cudaFuncSetAttribute(conv3_kernel,
                         cudaFuncAttributeMaxDynamicSharedMemorySize, conv3_smem);

    prep_kernel<<<64, 256>>>(conv2_w, conv3_w, fc1_w);

    conv1_kernel<<<BATCH / 2, 336>>>(x, conv1_w);

    conv2_kernel<<<BATCH / 4, 320>>>();          // bn1 folded in

    conv3_kernel<<<dim3(BATCH / 32, 2), 256, conv3_smem>>>(bn2_g, bn2_b);  // bn2 folded

    finalize_kernel<<<1, 128>>>(22, 120, (double)BATCH, 1e-5, bn3_g, bn3_b);

    fc_kernel<<<BATCH / 8, 256>>>(fc1_b, fc2_w, fc2_b, out);
}